// round 9
// baseline (speedup 1.0000x reference)
#include <cuda_runtime.h>
#include <cuda_fp16.h>
#include <stdint.h>

#define B_    64
#define NQ    1024
#define NK    1024
#define DH    128
#define BM    128
#define BN    64
#define NTHR  256
#define NT_K  16          // NK / BN key tiles
#define NITEMS 512        // B_ * (NQ/BM)
#define NWORK 304         // persistent CTAs (2 per SM, 152 SMs)
#define QKS   136         // half stride, Q/K tiles (272B: conflict-free ldmatrix)
#define VTS   72          // half stride, V^T tile  (144B: conflict-free ldmatrix)
#define KTILE (BN * QKS)  // 8704 halves per K tile
#define VTILE (DH * VTS)  // 9216 halves per V^T tile

// scale' = (1/sqrt(128)) * log2(e): QK scores come out in log2-domain
#define SCALE_L2E 0.1275174365f

// smem layout (halves): Q | K0 | K1 | V0 | V1
#define SOFF_Q  0
#define SOFF_K0 17408
#define SOFF_K1 26112
#define SOFF_V0 34816
#define SOFF_V1 44032
#define SMEM_HALVES 53248
// mbarrier tail (bytes from smem base)
#define MB_KFULL(s)  (SMEM_HALVES * 2 + (s) * 8)
#define MB_KEMPTY(s) (SMEM_HALVES * 2 + 16 + (s) * 8)
#define MB_VFULL(s)  (SMEM_HALVES * 2 + 32 + (s) * 8)
#define MB_VEMPTY(s) (SMEM_HALVES * 2 + 48 + (s) * 8)
#define SMEM_BYTES   (SMEM_HALVES * 2 + 64)

// ---- global fp16 scratch (pre-converted, smem-layout tiles) + work counter ----
__device__ half g_Kh[B_][NT_K][KTILE];
__device__ half g_Vt[B_][NT_K][VTILE];
__device__ int  g_ctr;

// ======================= helpers =======================

__device__ __forceinline__ void mma16816(float c[4], const uint32_t a[4],
                                         uint32_t b0, uint32_t b1) {
    asm volatile(
        "mma.sync.aligned.m16n8k16.row.col.f32.f16.f16.f32 "
        "{%0,%1,%2,%3}, {%4,%5,%6,%7}, {%8,%9}, {%0,%1,%2,%3};\n"
        : "+f"(c[0]), "+f"(c[1]), "+f"(c[2]), "+f"(c[3])
        : "r"(a[0]), "r"(a[1]), "r"(a[2]), "r"(a[3]), "r"(b0), "r"(b1));
}

#define LDSM4(R0, R1, R2, R3, ADDR)                                            \
    asm volatile("ldmatrix.sync.aligned.m8n8.x4.shared.b16 {%0,%1,%2,%3}, [%4];" \
                 : "=r"(R0), "=r"(R1), "=r"(R2), "=r"(R3) : "r"(ADDR))

__device__ __forceinline__ uint32_t s2u(const void* p) {
    return (uint32_t)__cvta_generic_to_shared(p);
}

__device__ __forceinline__ void cp16(void* smem_dst, const void* gsrc) {
    uint32_t s = s2u(smem_dst);
    asm volatile("cp.async.cg.shared.global [%0], [%1], 16;" :: "r"(s), "l"(gsrc));
}

#define MB_INIT(mb, cnt)                                                       \
    asm volatile("mbarrier.init.shared.b64 [%0], %1;"                          \
                 :: "r"((uint32_t)(mb)), "r"((uint32_t)(cnt)) : "memory")
#define MB_ARRIVE(mb)                                                          \
    asm volatile("mbarrier.arrive.shared.b64 _, [%0];"                         \
                 :: "r"((uint32_t)(mb)) : "memory")
// .noinc is load-bearing: the default form pre-increments the pending count
// (phase-neutral); .noinc makes the deferred arrive actually decrement, so
// 256 arrive-ons complete a count-256 barrier.
#define CPASYNC_MB_ARRIVE(mb)                                                  \
    asm volatile("cp.async.mbarrier.arrive.noinc.shared.b64 [%0];"             \
                 :: "r"((uint32_t)(mb)) : "memory")
#define MB_WAIT(mb, ph) do {                                                   \
    uint32_t _mb = (uint32_t)(mb), _ph = (uint32_t)(ph);                        \
    asm volatile("{\n\t.reg .pred P1;\n\t"                                      \
        "WL_%=:\n\t"                                                            \
        "mbarrier.try_wait.parity.acquire.cta.shared::cta.b64 P1, [%0], %1, 0x989680;\n\t" \
        "@P1 bra.uni WD_%=;\n\t"                                                \
        "bra.uni WL_%=;\n\t"                                                    \
        "WD_%=:\n\t}" :: "r"(_mb), "r"(_ph) : "memory");                        \
} while (0)

__device__ __forceinline__ uint32_t pack2(float x, float y) {
    __half2 h = __floats2half2_rn(x, y);
    return *reinterpret_cast<uint32_t*>(&h);
}
__device__ __forceinline__ uint32_t ex2h2(uint32_t x) {
    uint32_t y;
    asm("ex2.approx.f16x2 %0, %1;" : "=r"(y) : "r"(x));
    return y;
}
__device__ __forceinline__ uint32_t hadd2(uint32_t a, uint32_t b) {
    uint32_t c;
    asm("add.rn.f16x2 %0, %1, %2;" : "=r"(c) : "r"(a), "r"(b));
    return c;
}
__device__ __forceinline__ float hsum2f(uint32_t h) {
    __half2 v = *reinterpret_cast<__half2*>(&h);
    float2 f = __half22float2(v);
    return f.x + f.y;
}

// ======================= pre-pass: fp32 -> fp16 tiles =======================
__global__ void __launch_bounds__(NTHR)
prepass_kernel(const float* __restrict__ K, const float* __restrict__ V,
               const int* __restrict__ VL)
{
    const int t = blockIdx.x, b = blockIdx.y, tid = threadIdx.x;
    if (t == 0 && b == 0 && blockIdx.z == 0 && tid == 0) g_ctr = 0;
    if (t * BN >= VL[b]) return;

    if (blockIdx.z == 0) {
        const float4* Kg = reinterpret_cast<const float4*>(
            K + ((size_t)b * NK + (size_t)t * BN) * DH);
        __half2* dh = reinterpret_cast<__half2*>(g_Kh[b][t]);
        for (int i = tid; i < BN * DH / 4; i += NTHR) {
            int r = i >> 5;
            int c = (i & 31) << 2;
            float4 v = Kg[i];
            int h2 = (r * QKS + c) >> 1;
            dh[h2]     = __floats2half2_rn(v.x, v.y);
            dh[h2 + 1] = __floats2half2_rn(v.z, v.w);
        }
    } else {
        __shared__ float vs[BN][133];
        const float4* Vg = reinterpret_cast<const float4*>(
            V + ((size_t)b * NK + (size_t)t * BN) * DH);
        for (int i = tid; i < BN * DH / 4; i += NTHR) {
            int r = i >> 5;
            int c = (i & 31) << 2;
            float4 v = Vg[i];
            vs[r][c] = v.x; vs[r][c + 1] = v.y; vs[r][c + 2] = v.z; vs[r][c + 3] = v.w;
        }
        __syncthreads();
        __half2* dst = reinterpret_cast<__half2*>(g_Vt[b][t]);
        for (int i = tid; i < DH * BN / 2; i += NTHR) {
            int d  = i >> 5;
            int kp = i & 31;
            dst[d * (VTS / 2) + kp] = __floats2half2_rn(vs[2 * kp][d], vs[2 * kp + 1][d]);
        }
    }
}

// ======================= main attention kernel (persistent, mbarrier pipe) ==
// Separate K and V double-buffer rings. Full barriers (count 256) trip via
// cp.async.mbarrier.arrive.noinc; empty barriers (count 8) via one arrive per
// warp after its last read. No __syncthreads in the tile loop -> warps stagger,
// softmax of one warp overlaps MMAs of another, V arrival never gates QK.

__global__ void __launch_bounds__(NTHR, 2)
attn_kernel(const float* __restrict__ Q, const int* __restrict__ VL,
            float* __restrict__ O)
{
    extern __shared__ __align__(16) half smem[];
    const uint32_t smb = s2u(smem);
    __shared__ int s_item;

    const int tid  = threadIdx.x;
    const int warp = tid >> 5;
    const int lane = tid & 31;
    const int g    = lane >> 2;
    const int q4   = lane & 3;

    const int a_row = (lane & 15);
    const int a_col = (lane & 16) ? 8 : 0;
    const int b_row = (lane & 7) + ((lane & 16) ? 8 : 0);
    const int b_col = (lane & 8);
    const int ra    = warp * 16;

    if (tid == 0) {
        MB_INIT(smb + MB_KFULL(0), NTHR);  MB_INIT(smb + MB_KFULL(1), NTHR);
        MB_INIT(smb + MB_VFULL(0), NTHR);  MB_INIT(smb + MB_VFULL(1), NTHR);
        MB_INIT(smb + MB_KEMPTY(0), 8);    MB_INIT(smb + MB_KEMPTY(1), 8);
        MB_INIT(smb + MB_VEMPTY(0), 8);    MB_INIT(smb + MB_VEMPTY(1), 8);
    }
    __syncthreads();

    // ring cursors (persist across items): writers start phase 1, readers 0
    int kws = 0, kwp = 1, vws = 0, vwp = 1;
    int krs = 0, krp = 0, vrs = 0, vrp = 0;

    for (;;) {
        __syncthreads();
        if (tid == 0) s_item = atomicAdd(&g_ctr, 1);
        __syncthreads();
        const int item = s_item;
        if (item >= NITEMS) break;
        const int b  = item & (B_ - 1);
        const int qt = item >> 6;

        const int Lb = VL[b];
        const int nt = (Lb + BN - 1) / BN;

        // ---- prologue: issue K(0),V(0) [+K(1),V(1)], convert Q ----
        {
            MB_WAIT(smb + MB_KEMPTY(kws), kwp);
            half* dst = smem + (kws ? SOFF_K1 : SOFF_K0);
            for (int i = tid * 8; i < KTILE; i += NTHR * 8) cp16(dst + i, g_Kh[b][0] + i);
            CPASYNC_MB_ARRIVE(smb + MB_KFULL(kws));
            kws ^= 1; if (!kws) kwp ^= 1;
        }
        {
            MB_WAIT(smb + MB_VEMPTY(vws), vwp);
            half* dst = smem + (vws ? SOFF_V1 : SOFF_V0);
            for (int i = tid * 8; i < VTILE; i += NTHR * 8) cp16(dst + i, g_Vt[b][0] + i);
            CPASYNC_MB_ARRIVE(smb + MB_VFULL(vws));
            vws ^= 1; if (!vws) vwp ^= 1;
        }
        {
            const float4* Qg = reinterpret_cast<const float4*>(
                Q + ((size_t)b * NQ + (size_t)qt * BM) * DH);
            __half2* Qh2 = reinterpret_cast<__half2*>(smem + SOFF_Q);
            for (int i = tid; i < BM * DH / 4; i += NTHR) {
                int r = i >> 5;
                int c = (i & 31) << 2;
                float4 v = Qg[i];
                int h2 = (r * QKS + c) >> 1;
                Qh2[h2]     = __floats2half2_rn(v.x * SCALE_L2E, v.y * SCALE_L2E);
                Qh2[h2 + 1] = __floats2half2_rn(v.z * SCALE_L2E, v.w * SCALE_L2E);
            }
        }
        if (nt > 1) {
            MB_WAIT(smb + MB_KEMPTY(kws), kwp);
            half* dst = smem + (kws ? SOFF_K1 : SOFF_K0);
            for (int i = tid * 8; i < KTILE; i += NTHR * 8) cp16(dst + i, g_Kh[b][1] + i);
            CPASYNC_MB_ARRIVE(smb + MB_KFULL(kws));
            kws ^= 1; if (!kws) kwp ^= 1;

            MB_WAIT(smb + MB_VEMPTY(vws), vwp);
            half* dst2 = smem + (vws ? SOFF_V1 : SOFF_V0);
            for (int i = tid * 8; i < VTILE; i += NTHR * 8) cp16(dst2 + i, g_Vt[b][1] + i);
            CPASYNC_MB_ARRIVE(smb + MB_VFULL(vws));
            vws ^= 1; if (!vws) vwp ^= 1;
        }
        __syncthreads();   // Q visibility before any warp's QK

        // ---- state ----
        float l0 = 0.f, l1 = 0.f;
        float o[16][4];
        #pragma unroll
        for (int d = 0; d < 16; d++) { o[d][0] = o[d][1] = o[d][2] = o[d][3] = 0.f; }

        int wt = (nt > 1) ? 2 : 1;   // next tile index to write

        for (int kt = 0; kt < nt; kt++) {
            // ---- QK: wait K(kt), consume, release K buffer ----
            MB_WAIT(smb + MB_KFULL(krs), krp);
            half* Kh = smem + (krs ? SOFF_K1 : SOFF_K0);

            float s[8][4];
            #pragma unroll
            for (int j = 0; j < 8; j++) { s[j][0] = s[j][1] = s[j][2] = s[j][3] = 0.f; }

            #pragma unroll
            for (int ks = 0; ks < 8; ks++) {
                uint32_t ah[4];
                const half* qa = smem + SOFF_Q + (ra + a_row) * QKS + ks * 16 + a_col;
                LDSM4(ah[0], ah[1], ah[2], ah[3], s2u(qa));
                #pragma unroll
                for (int jp = 0; jp < 4; jp++) {
                    uint32_t kh[4];
                    const half* ka = Kh + (jp * 16 + b_row) * QKS + ks * 16 + b_col;
                    LDSM4(kh[0], kh[1], kh[2], kh[3], s2u(ka));
                    mma16816(s[2 * jp],     ah, kh[0], kh[1]);
                    mma16816(s[2 * jp + 1], ah, kh[2], kh[3]);
                }
            }
            __syncwarp();
            if (lane == 0) MB_ARRIVE(smb + MB_KEMPTY(krs));
            krs ^= 1; if (!krs) krp ^= 1;

            const bool dow = (wt < nt);
            // ---- issue K(wt) while softmax/PV run ----
            if (dow) {
                MB_WAIT(smb + MB_KEMPTY(kws), kwp);
                half* dst = smem + (kws ? SOFF_K1 : SOFF_K0);
                for (int i = tid * 8; i < KTILE; i += NTHR * 8)
                    cp16(dst + i, g_Kh[b][wt] + i);
                CPASYNC_MB_ARRIVE(smb + MB_KFULL(kws));
                kws ^= 1; if (!kws) kwp ^= 1;
            }

            // ---- mask tail keys ----
            if ((kt + 1) * BN > Lb) {
                int kb = kt * BN;
                #pragma unroll
                for (int j = 0; j < 8; j++) {
                    int k0 = kb + j * 8 + q4 * 2;
                    if (k0     >= Lb) { s[j][0] = -1e30f; s[j][2] = -1e30f; }
                    if (k0 + 1 >= Lb) { s[j][1] = -1e30f; s[j][3] = -1e30f; }
                }
            }

            // ---- p = 2^s in f16x2; HADD2-tree row sums, f32 accumulate ----
            uint32_t p0[8], p1[8];
            #pragma unroll
            for (int j = 0; j < 8; j++) {
                p0[j] = ex2h2(pack2(s[j][0], s[j][1]));
                p1[j] = ex2h2(pack2(s[j][2], s[j][3]));
            }
            {
                uint32_t a = hadd2(hadd2(hadd2(p0[0], p0[1]), hadd2(p0[2], p0[3])),
                                   hadd2(hadd2(p0[4], p0[5]), hadd2(p0[6], p0[7])));
                uint32_t c = hadd2(hadd2(hadd2(p1[0], p1[1]), hadd2(p1[2], p1[3])),
                                   hadd2(hadd2(p1[4], p1[5]), hadd2(p1[6], p1[7])));
                l0 += hsum2f(a);
                l1 += hsum2f(c);
            }

            // ---- PV: wait V(kt), consume, release V buffer ----
            MB_WAIT(smb + MB_VFULL(vrs), vrp);
            half* Vt = smem + (vrs ? SOFF_V1 : SOFF_V0);

            #pragma unroll
            for (int ks = 0; ks < 4; ks++) {
                uint32_t pa[4];
                pa[0] = p0[2 * ks];
                pa[1] = p1[2 * ks];
                pa[2] = p0[2 * ks + 1];
                pa[3] = p1[2 * ks + 1];
                #pragma unroll
                for (int dp = 0; dp < 8; dp++) {
                    uint32_t vb[4];
                    const half* va = Vt + (dp * 16 + b_row) * VTS + ks * 16 + b_col;
                    LDSM4(vb[0], vb[1], vb[2], vb[3], s2u(va));
                    mma16816(o[2 * dp],     pa, vb[0], vb[1]);
                    mma16816(o[2 * dp + 1], pa, vb[2], vb[3]);
                }
            }
            __syncwarp();
            if (lane == 0) MB_ARRIVE(smb + MB_VEMPTY(vrs));
            vrs ^= 1; if (!vrs) vrp ^= 1;

            // ---- issue V(wt) ----
            if (dow) {
                MB_WAIT(smb + MB_VEMPTY(vws), vwp);
                half* dst = smem + (vws ? SOFF_V1 : SOFF_V0);
                for (int i = tid * 8; i < VTILE; i += NTHR * 8)
                    cp16(dst + i, g_Vt[b][wt] + i);
                CPASYNC_MB_ARRIVE(smb + MB_VFULL(vws));
                vws ^= 1; if (!vws) vwp ^= 1;
                wt++;
            }
        }

        // ---- epilogue: quad reduction for l, normalize + store ----
        l0 += __shfl_xor_sync(0xffffffffu, l0, 1);
        l0 += __shfl_xor_sync(0xffffffffu, l0, 2);
        l1 += __shfl_xor_sync(0xffffffffu, l1, 1);
        l1 += __shfl_xor_sync(0xffffffffu, l1, 2);
        float inv0 = 1.0f / l0, inv1 = 1.0f / l1;
        size_t row0 = ((size_t)b * NQ + (size_t)qt * BM + ra + g) * DH;
        size_t row1 = row0 + (size_t)8 * DH;
        #pragma unroll
        for (int d = 0; d < 16; d++) {
            int c = d * 8 + q4 * 2;
            *reinterpret_cast<float2*>(O + row0 + c) =
                make_float2(o[d][0] * inv0, o[d][1] * inv0);
            *reinterpret_cast<float2*>(O + row1 + c) =
                make_float2(o[d][2] * inv1, o[d][3] * inv1);
        }
    }
}

// ======================= launch =======================

extern "C" void kernel_launch(void* const* d_in, const int* in_sizes, int n_in,
                              void* d_out, int out_size) {
    (void)in_sizes; (void)n_in; (void)out_size;
    const float* Q  = (const float*)d_in[0];
    const float* K  = (const float*)d_in[1];
    const float* V  = (const float*)d_in[2];
    const int*   VL = (const int*)d_in[3];
    float* O = (float*)d_out;

    dim3 pgrid(NT_K, B_, 2);
    prepass_kernel<<<pgrid, NTHR>>>(K, V, VL);

    static int configured = 0;
    if (!configured) {
        cudaFuncSetAttribute(attn_kernel, cudaFuncAttributeMaxDynamicSharedMemorySize,
                             SMEM_BYTES);
        configured = 1;
    }
    attn_kernel<<<NWORK, NTHR, SMEM_BYTES>>>(Q, VL, O);
}